// round 9
// baseline (speedup 1.0000x reference)
#include <cuda_runtime.h>
#include <math.h>

#define NB  16
#define C   256
#define H   80
#define W   80
#define MIP 8
#define L   160            // H + W
#define BN_EPS 1e-5f

// Scratch (device globals: no allocations allowed)
__device__ float g_y [NB * C * L];   // [n][c][l]: l<80 row means (x_h), l>=80 col means (x_w)
__device__ float g_ah[NB * C * H];
__device__ float g_aw[NB * C * W];

__device__ __forceinline__ float fsig(float v) { return 1.f / (1.f + __expf(-v)); }

// 32-byte load with L2 evict-last priority (sm_103a requires v8.b32 for this hint).
// Pins x's lines high in the L2 LRU so the k3 out-write stream (evict-first
// __stcs) victimizes its own lines instead of x's.
__device__ __forceinline__ void ldg_el8(const float* p, float4& a, float4& b) {
    unsigned r0, r1, r2, r3, r4, r5, r6, r7;
    asm volatile("ld.global.nc.L2::evict_last.v8.b32 {%0,%1,%2,%3,%4,%5,%6,%7}, [%8];"
                 : "=r"(r0), "=r"(r1), "=r"(r2), "=r"(r3),
                   "=r"(r4), "=r"(r5), "=r"(r6), "=r"(r7)
                 : "l"(p));
    a.x = __uint_as_float(r0); a.y = __uint_as_float(r1);
    a.z = __uint_as_float(r2); a.w = __uint_as_float(r3);
    b.x = __uint_as_float(r4); b.y = __uint_as_float(r5);
    b.z = __uint_as_float(r6); b.w = __uint_as_float(r7);
}

// ---------------------------------------------------------------------------
// k1: one block (320 thr) per plane. Threads 0..159 load: 10 float8 col-groups
// x 16 row-groups, 5 rows each (MLP 5, evict_last). Column partials in regs,
// small partials through padded smem; threads 0..79 / 160..239 reduce.
// ---------------------------------------------------------------------------
__global__ __launch_bounds__(320) void k1_means(const float* __restrict__ x) {
    __shared__ float s_row[H][11];     // 10 horizontal 8-sums per row; 11: gcd(11,32)=1
    __shared__ float s_col[W][17];     // 16 column partials per col;   17: gcd(17,32)=1
    const int plane = blockIdx.x;
    const int t  = threadIdx.x;
    const float* __restrict__ xp = x + (size_t)plane * (H * W);

    if (t < 160) {
        const int q8 = t % 10;         // float8 column group: cols 8q8..8q8+7
        const int rg = t / 10;         // row group 0..15
        float c0=0.f,c1=0.f,c2=0.f,c3=0.f,c4=0.f,c5=0.f,c6=0.f,c7=0.f;
        #pragma unroll
        for (int i = 0; i < 5; i++) {
            int r = i * 16 + rg;
            float4 a, b;
            ldg_el8(xp + r * W + q8 * 8, a, b);
            c0 += a.x; c1 += a.y; c2 += a.z; c3 += a.w;
            c4 += b.x; c5 += b.y; c6 += b.z; c7 += b.w;
            s_row[r][q8] = (a.x + a.y + a.z + a.w) + (b.x + b.y + b.z + b.w);
        }
        s_col[8*q8+0][rg] = c0; s_col[8*q8+1][rg] = c1;
        s_col[8*q8+2][rg] = c2; s_col[8*q8+3][rg] = c3;
        s_col[8*q8+4][rg] = c4; s_col[8*q8+5][rg] = c5;
        s_col[8*q8+6][rg] = c6; s_col[8*q8+7][rg] = c7;
    }
    __syncthreads();

    const float inv80 = 1.0f / 80.0f;
    if (t < H) {
        float s = 0.f;
        #pragma unroll
        for (int j = 0; j < 10; j++) s += s_row[t][j];
        g_y[(size_t)plane * L + t] = s * inv80;          // x_h (row mean)
    } else if (t >= 160 && t < 160 + W) {
        int col = t - 160;
        float s = 0.f;
        #pragma unroll
        for (int g = 0; g < 16; g++) s += s_col[col][g];
        g_y[(size_t)plane * L + H + col] = s * inv80;    // x_w (col mean)
    }
}

// ---------------------------------------------------------------------------
// k2: grid (16, 2), block 320. GEMM1 split-K (MLP 8), smem combine, BN+swish;
// GEMM2 register-hoisted. Unchanged from R7.
// ---------------------------------------------------------------------------
__global__ __launch_bounds__(320) void k2_attn(const float* __restrict__ w_fc,
                                               const float* __restrict__ bn_gamma,
                                               const float* __restrict__ bn_beta,
                                               const float* __restrict__ bn_mean,
                                               const float* __restrict__ bn_var,
                                               const float* __restrict__ w_h,
                                               const float* __restrict__ w_w) {
    __shared__ float ys[MIP * L];        // swished bottleneck (5 KB)
    __shared__ float wfcT[C * MIP];      // w_fc transposed (8 KB)
    __shared__ float ps[2 * MIP * L];    // split-K partials (10 KB)
    const int n = blockIdx.x;
    const int t = threadIdx.x;

    if (t < C) {
        #pragma unroll
        for (int m = 0; m < MIP; m++) wfcT[t * MIP + m] = w_fc[m * C + t];
    }
    __syncthreads();

    const float* __restrict__ yb = g_y + (size_t)n * C * L;
    {
        const int l    = t % L;
        const int half = t / L;                          // 0 or 1
        const int c0   = half * (C / 2);
        float acc[MIP];
        #pragma unroll
        for (int m = 0; m < MIP; m++) acc[m] = 0.f;
        #pragma unroll 8
        for (int c = 0; c < C / 2; c++) {
            float v = yb[(c0 + c) * L + l];              // coalesced across threads
            const float4* wr = (const float4*)(wfcT + (c0 + c) * MIP);
            float4 a = wr[0], b = wr[1];
            acc[0] = fmaf(a.x, v, acc[0]); acc[1] = fmaf(a.y, v, acc[1]);
            acc[2] = fmaf(a.z, v, acc[2]); acc[3] = fmaf(a.w, v, acc[3]);
            acc[4] = fmaf(b.x, v, acc[4]); acc[5] = fmaf(b.y, v, acc[5]);
            acc[6] = fmaf(b.z, v, acc[6]); acc[7] = fmaf(b.w, v, acc[7]);
        }
        #pragma unroll
        for (int m = 0; m < MIP; m++) ps[half * MIP * L + m * L + l] = acc[m];
    }
    __syncthreads();

    if (t < L) {
        #pragma unroll
        for (int m = 0; m < MIP; m++) {
            float s  = ps[m * L + t] + ps[MIP * L + m * L + t];
            float iv = bn_gamma[m] * rsqrtf(bn_var[m] + BN_EPS);
            float vv = s * iv + (bn_beta[m] - bn_mean[m] * iv);
            ys[m * L + t] = vv * fsig(vv);
        }
    }
    __syncthreads();

    const int l  = t % 80;
    const int cg = t / 80;                               // 0..3
    const int c0 = (blockIdx.y * 4 + cg) * 32;
    float yh[MIP], yw[MIP];
    #pragma unroll
    for (int m = 0; m < MIP; m++) { yh[m] = ys[m * L + l]; yw[m] = ys[m * L + H + l]; }

    float* __restrict__ ahp = g_ah + (size_t)n * C * H;
    float* __restrict__ awp = g_aw + (size_t)n * C * W;
    #pragma unroll 4
    for (int c = c0; c < c0 + 32; c++) {
        const float4* wh4 = (const float4*)(w_h + c * MIP);
        const float4* ww4 = (const float4*)(w_w + c * MIP);
        float4 ha = wh4[0], hb = wh4[1];
        float4 wa = ww4[0], wb = ww4[1];
        float sh = 0.f, sw = 0.f;
        sh = fmaf(ha.x, yh[0], sh); sh = fmaf(ha.y, yh[1], sh);
        sh = fmaf(ha.z, yh[2], sh); sh = fmaf(ha.w, yh[3], sh);
        sh = fmaf(hb.x, yh[4], sh); sh = fmaf(hb.y, yh[5], sh);
        sh = fmaf(hb.z, yh[6], sh); sh = fmaf(hb.w, yh[7], sh);
        sw = fmaf(wa.x, yw[0], sw); sw = fmaf(wa.y, yw[1], sw);
        sw = fmaf(wa.z, yw[2], sw); sw = fmaf(wa.w, yw[3], sw);
        sw = fmaf(wb.x, yw[4], sw); sw = fmaf(wb.y, yw[5], sw);
        sw = fmaf(wb.z, yw[6], sw); sw = fmaf(wb.w, yw[7], sw);
        ahp[c * H + l] = fsig(sh);
        awp[c * W + l] = fsig(sw);
    }
}

// ---------------------------------------------------------------------------
// k3: 1024 blocks x 320 thr. Each block owns 4 consecutive planes (3200 float8),
// DESCENDING plane order. a-maps staged in smem; x read evict_last float8
// (MLP-5 batches), out written as evict-first streaming float4 pairs.
// ---------------------------------------------------------------------------
__global__ __launch_bounds__(320) void k3_apply(const float* __restrict__ x,
                                                float* __restrict__ out) {
    __shared__ float s_ah[4 * H];        // 4 planes of a_h (320 floats)
    __shared__ float s_aw[4 * W];        // 4 planes of a_w (320 floats)
    const int pb  = 1023 - blockIdx.x;   // 4-plane group, descending
    const int tid = threadIdx.x;
    const size_t base8 = (size_t)pb * 3200;  // float8 base

    s_ah[tid] = g_ah[pb * 4 * H + tid];
    s_aw[tid] = g_aw[pb * 4 * W + tid];
    __syncthreads();

    float4* __restrict__ o4 = (float4*)out;

    #pragma unroll
    for (int batch = 0; batch < 2; batch++) {
        float4 xa[5], xb[5];
        int    idx[5];
        #pragma unroll
        for (int jj = 0; jj < 5; jj++) {
            idx[jj] = (batch * 5 + jj) * 320 + tid;      // [0, 3200)
            ldg_el8(x + (base8 + idx[jj]) * 8, xa[jj], xb[jj]);
        }
        #pragma unroll
        for (int jj = 0; jj < 5; jj++) {
            const int v   = idx[jj];
            const int lp  = v / 800;                     // local plane 0..3
            const int rem = v - lp * 800;
            const int hh  = rem / 10;
            const int q8  = rem - hh * 10;
            const float  ah  = s_ah[lp * H + hh];
            const float4 w0  = *(const float4*)(s_aw + lp * W + q8 * 8);
            const float4 w1  = *(const float4*)(s_aw + lp * W + q8 * 8 + 4);
            float4 r0, r1;
            r0.x = xa[jj].x * (ah * w0.x); r0.y = xa[jj].y * (ah * w0.y);
            r0.z = xa[jj].z * (ah * w0.z); r0.w = xa[jj].w * (ah * w0.w);
            r1.x = xb[jj].x * (ah * w1.x); r1.y = xb[jj].y * (ah * w1.y);
            r1.z = xb[jj].z * (ah * w1.z); r1.w = xb[jj].w * (ah * w1.w);
            const size_t g4 = (base8 + v) * 2;           // float4 index
            __stcs(o4 + g4,     r0);
            __stcs(o4 + g4 + 1, r1);
        }
    }
}

// ---------------------------------------------------------------------------
extern "C" void kernel_launch(void* const* d_in, const int* in_sizes, int n_in,
                              void* d_out, int out_size) {
    const float* x        = (const float*)d_in[0];
    const float* w_fc     = (const float*)d_in[1];
    const float* bn_gamma = (const float*)d_in[2];
    const float* bn_beta  = (const float*)d_in[3];
    const float* bn_mean  = (const float*)d_in[4];
    const float* bn_var   = (const float*)d_in[5];
    const float* w_h      = (const float*)d_in[6];
    const float* w_w      = (const float*)d_in[7];
    float* out = (float*)d_out;

    k1_means<<<NB * C, 320>>>(x);
    k2_attn<<<dim3(NB, 2), 320>>>(w_fc, bn_gamma, bn_beta, bn_mean, bn_var, w_h, w_w);
    k3_apply<<<1024, 320>>>(x, out);
}